// round 2
// baseline (speedup 1.0000x reference)
#include <cuda_runtime.h>
#include <cuda_fp16.h>
#include <cuda_bf16.h>
#include <cstdint>

// ---------------------------------------------------------------------------
// InversionModel: multi-scale conv frontend + 4x shared-weight 6432x6432 linear
// Strategy R1: fp16 mma.sync GEMM (fp32 accum), cp.async 4-stage pipeline.
// ---------------------------------------------------------------------------

#define BM 128
#define BN 128
#define BK 32
#define STAGES 4
#define LDSK (BK + 8)          // 40 halves per row (pad kills LDS bank conflicts)
#define M_DIM 2048
#define N_DIM 6432
#define K_DIM 6432
#define SMEM_BYTES (2 * STAGES * BM * LDSK * (int)sizeof(__half))   // 81920

// Scratch (static device arrays; no allocation allowed)
__device__ __align__(16) __half g_act0[(size_t)M_DIM * N_DIM];
__device__ __align__(16) __half g_act1[(size_t)M_DIM * N_DIM];
__device__ __align__(16) __half g_wh[(size_t)N_DIM * K_DIM];

// ------------------------------ helpers ------------------------------------

__device__ __forceinline__ void cp16(void* dst, const void* src, bool pred) {
    uint32_t s = (uint32_t)__cvta_generic_to_shared(dst);
    int sz = pred ? 16 : 0;
    asm volatile("cp.async.cg.shared.global [%0], [%1], 16, %2;\n"
                 :: "r"(s), "l"(src), "r"(sz));
}

__device__ __forceinline__ void mma16816(float* c, const uint32_t* a, const uint32_t* b) {
    asm volatile(
        "mma.sync.aligned.m16n8k16.row.col.f32.f16.f16.f32 "
        "{%0,%1,%2,%3}, {%4,%5,%6,%7}, {%8,%9}, {%0,%1,%2,%3};\n"
        : "+f"(c[0]), "+f"(c[1]), "+f"(c[2]), "+f"(c[3])
        : "r"(a[0]), "r"(a[1]), "r"(a[2]), "r"(a[3]), "r"(b[0]), "r"(b[1]));
}

// ------------------------- weight fp32 -> fp16 ------------------------------

__global__ void convert_w_kernel(const float* __restrict__ w, __half* __restrict__ wh,
                                 long long n) {
    long long i = ((long long)blockIdx.x * blockDim.x + threadIdx.x) * 4;
    if (i < n) {
        float4 v = *(const float4*)(w + i);
        *(__half2*)(wh + i)     = __floats2half2_rn(v.x, v.y);
        *(__half2*)(wh + i + 2) = __floats2half2_rn(v.z, v.w);
    }
}

// ------------------------------ frontend -----------------------------------
// One block = (batch, scale). coarse_grain -> conv1+relu+pool -> conv2+relu+pool
// writes fp16 activations at [b, c2*201 + scale_off + q].

__global__ void frontend_kernel(const float* __restrict__ x,
                                const float* __restrict__ w1, const float* __restrict__ b1,
                                const float* __restrict__ w2, const float* __restrict__ b2,
                                __half* __restrict__ f) {
    int b = blockIdx.x;
    int sidx = blockIdx.y;           // 0,1,2 -> s = 1,2,4
    int s = 1 << sidx;
    int Lc = 480 >> sidx;
    int off = (sidx == 0) ? 0 : (sidx == 1 ? 117 : 174);

    __shared__ float xc[4 * 480];
    __shared__ float p1[16 * 238];
    __shared__ float w1s[320], w2s[2560];
    __shared__ float b1s[16], b2s[32];

    int tid = threadIdx.x;           // 128 threads
    for (int i = tid; i < 320; i += 128) w1s[i] = w1[i];
    for (int i = tid; i < 2560; i += 128) w2s[i] = w2[i];
    if (tid < 16) b1s[tid] = b1[tid];
    if (tid < 32) b2s[tid] = b2[tid];

    const float* xb = x + (size_t)b * 4 * 480;
    float inv_s = 1.0f / (float)s;
    for (int i = tid; i < 4 * Lc; i += 128) {
        int c = i / Lc, p = i % Lc;
        float sum = 0.f;
        for (int j = 0; j < s; ++j) sum += xb[c * 480 + p * s + j];
        xc[c * Lc + p] = sum * inv_s;
    }
    __syncthreads();

    int L1 = Lc - 4;
    int L1p = L1 >> 1;               // 238 / 118 / 58
    for (int i = tid; i < 16 * L1p; i += 128) {
        int o = i / L1p, q = i % L1p;
        float best = -1e30f;
        #pragma unroll
        for (int pp = 0; pp < 2; ++pp) {
            int p = 2 * q + pp;
            float acc = b1s[o];
            #pragma unroll
            for (int c = 0; c < 4; ++c)
                #pragma unroll
                for (int k = 0; k < 5; ++k)
                    acc += xc[c * Lc + p + k] * w1s[o * 20 + c * 5 + k];
            best = fmaxf(best, acc);
        }
        p1[o * L1p + q] = fmaxf(best, 0.f);
    }
    __syncthreads();

    int L2 = (L1p - 4) >> 1;         // 117 / 57 / 27
    __half* fb = f + (size_t)b * N_DIM;
    for (int i = tid; i < 32 * L2; i += 128) {
        int o2 = i / L2, q = i % L2;
        float best = -1e30f;
        #pragma unroll
        for (int pp = 0; pp < 2; ++pp) {
            int p = 2 * q + pp;
            float acc = b2s[o2];
            #pragma unroll
            for (int c1 = 0; c1 < 16; ++c1)
                #pragma unroll
                for (int k = 0; k < 5; ++k)
                    acc += p1[c1 * L1p + p + k] * w2s[o2 * 80 + c1 * 5 + k];
            best = fmaxf(best, acc);
        }
        fb[o2 * 201 + off + q] = __float2half_rn(fmaxf(best, 0.f));
    }
}

// ------------------------------- GEMM --------------------------------------
// Out[m,n] = relu( sum_k A[m,k]*W[n,k] + bias[n] ), fp16 in, fp32 acc, fp16 out.
// 128x128x32 tiles, 8 warps (2x4), warp tile 64x32, m16n8k16 HMMA.

extern __shared__ __half dynsmem[];

__global__ __launch_bounds__(256, 2)
void gemm_relu_kernel(const __half* __restrict__ A, const __half* __restrict__ W,
                      const float* __restrict__ bias, __half* __restrict__ Out) {
    __half* sA = dynsmem;                                  // [STAGES][BM][LDSK]
    __half* sB = dynsmem + STAGES * BM * LDSK;             // [STAGES][BN][LDSK]
#define AS(st, r, c) sA[((st) * BM + (r)) * LDSK + (c)]
#define BS(st, r, c) sB[((st) * BN + (r)) * LDSK + (c)]

    const int tid = threadIdx.x;
    const int bm = blockIdx.y * BM;
    const int bn = blockIdx.x * BN;
    const int warp = tid >> 5, lane = tid & 31;
    const int wm = (warp >> 2) * 64;
    const int wn = (warp & 3) * 32;
    const int g = lane >> 2, tg = lane & 3;

    const int lrow = tid >> 2;          // 0..63
    const int lcol = (tid & 3) * 8;     // 0,8,16,24

    const __half* Ag = A + (size_t)(bm + lrow) * K_DIM + lcol;
    const size_t A64 = (size_t)64 * K_DIM;
    int nrow0 = bn + lrow, nrow1 = bn + lrow + 64;
    bool v0 = nrow0 < N_DIM, v1 = nrow1 < N_DIM;
    const __half* Wg0 = W + (size_t)(v0 ? nrow0 : N_DIM - 1) * K_DIM + lcol;
    const __half* Wg1 = W + (size_t)(v1 ? nrow1 : N_DIM - 1) * K_DIM + lcol;

#define LOAD_STAGE(st, k0) do {                           \
        cp16(&AS(st, lrow, lcol),      Ag + (k0), true);  \
        cp16(&AS(st, lrow + 64, lcol), Ag + A64 + (k0), true); \
        cp16(&BS(st, lrow, lcol),      Wg0 + (k0), v0);   \
        cp16(&BS(st, lrow + 64, lcol), Wg1 + (k0), v1);   \
    } while (0)

    float acc[4][4][4];
    #pragma unroll
    for (int mt = 0; mt < 4; ++mt)
        #pragma unroll
        for (int nt = 0; nt < 4; ++nt)
            #pragma unroll
            for (int i = 0; i < 4; ++i) acc[mt][nt][i] = 0.f;

    #pragma unroll
    for (int st = 0; st < STAGES - 1; ++st) {
        LOAD_STAGE(st, st * BK);
        asm volatile("cp.async.commit_group;\n");
    }

    const int NK = K_DIM / BK;   // 201
    for (int kt = 0; kt < NK; ++kt) {
        asm volatile("cp.async.wait_group %0;\n" :: "n"(STAGES - 2));
        __syncthreads();
        int st = kt & (STAGES - 1);
        int knext = kt + STAGES - 1;
        if (knext < NK) LOAD_STAGE(knext & (STAGES - 1), knext * BK);
        asm volatile("cp.async.commit_group;\n");

        #pragma unroll
        for (int ks = 0; ks < 2; ++ks) {
            const int kk = ks * 16 + tg * 2;
            uint32_t afr[4][4], bfr[4][2];
            #pragma unroll
            for (int mt = 0; mt < 4; ++mt) {
                const __half* p = &AS(st, wm + mt * 16 + g, kk);
                afr[mt][0] = *(const uint32_t*)(p);
                afr[mt][1] = *(const uint32_t*)(p + 8 * LDSK);
                afr[mt][2] = *(const uint32_t*)(p + 8);
                afr[mt][3] = *(const uint32_t*)(p + 8 * LDSK + 8);
            }
            #pragma unroll
            for (int nt = 0; nt < 4; ++nt) {
                const __half* p = &BS(st, wn + nt * 8 + g, kk);
                bfr[nt][0] = *(const uint32_t*)(p);
                bfr[nt][1] = *(const uint32_t*)(p + 8);
            }
            #pragma unroll
            for (int mt = 0; mt < 4; ++mt)
                #pragma unroll
                for (int nt = 0; nt < 4; ++nt)
                    mma16816(acc[mt][nt], afr[mt], bfr[nt]);
        }
    }

    // Epilogue: bias + relu + fp16 store
    #pragma unroll
    for (int mt = 0; mt < 4; ++mt) {
        int row = bm + wm + mt * 16 + g;
        #pragma unroll
        for (int nt = 0; nt < 4; ++nt) {
            int col = bn + wn + nt * 8 + tg * 2;
            if (col < N_DIM) {
                float2 bb = *(const float2*)(bias + col);
                float v0a = fmaxf(acc[mt][nt][0] + bb.x, 0.f);
                float v1a = fmaxf(acc[mt][nt][1] + bb.y, 0.f);
                float v2a = fmaxf(acc[mt][nt][2] + bb.x, 0.f);
                float v3a = fmaxf(acc[mt][nt][3] + bb.y, 0.f);
                *(__half2*)(Out + (size_t)row * N_DIM + col)       = __floats2half2_rn(v0a, v1a);
                *(__half2*)(Out + (size_t)(row + 8) * N_DIM + col) = __floats2half2_rn(v2a, v3a);
            }
        }
    }
#undef AS
#undef BS
#undef LOAD_STAGE
}

// ------------------------------- head --------------------------------------
// out[b, j] = sum_k f[b,k]*wo[j,k] + bo[j], 5 warps per block (one per j).

__global__ void head_kernel(const __half* __restrict__ f, const float* __restrict__ wo,
                            const float* __restrict__ bo, float* __restrict__ out) {
    int b = blockIdx.x;
    int w = threadIdx.x >> 5;        // 0..4
    int lane = threadIdx.x & 31;
    const __half* fb = f + (size_t)b * N_DIM;
    const float* wr = wo + (size_t)w * N_DIM;
    float acc = 0.f;
    for (int k = lane * 2; k < N_DIM; k += 64) {
        __half2 h = *(const __half2*)(fb + k);
        float2 wv = *(const float2*)(wr + k);
        acc += __half2float(h.x) * wv.x + __half2float(h.y) * wv.y;
    }
    #pragma unroll
    for (int o = 16; o > 0; o >>= 1) acc += __shfl_xor_sync(0xffffffffu, acc, o);
    if (lane == 0) out[b * 5 + w] = acc + bo[w];
}

// ------------------------------ launch -------------------------------------

extern "C" void kernel_launch(void* const* d_in, const int* in_sizes, int n_in,
                              void* d_out, int out_size) {
    (void)in_sizes; (void)n_in; (void)out_size;
    const float* x  = (const float*)d_in[0];
    const float* w1 = (const float*)d_in[1];
    const float* b1 = (const float*)d_in[2];
    const float* w2 = (const float*)d_in[3];
    const float* b2 = (const float*)d_in[4];
    const float* wl = (const float*)d_in[5];
    const float* bl = (const float*)d_in[6];
    const float* wo = (const float*)d_in[7];
    const float* bo = (const float*)d_in[8];
    float* out = (float*)d_out;

    __half *fa, *fb, *wh;
    cudaGetSymbolAddress((void**)&fa, g_act0);
    cudaGetSymbolAddress((void**)&fb, g_act1);
    cudaGetSymbolAddress((void**)&wh, g_wh);

    // weight conversion (fp32 -> fp16), 41,370,624 elements
    long long nW = (long long)N_DIM * K_DIM;
    convert_w_kernel<<<(unsigned)((nW / 4 + 255) / 256), 256>>>(wl, wh, nW);

    // frontend: (batch, scale) blocks
    frontend_kernel<<<dim3(2048, 3), 128>>>(x, w1, b1, w2, b2, fa);

    cudaFuncSetAttribute(gemm_relu_kernel,
                         cudaFuncAttributeMaxDynamicSharedMemorySize, SMEM_BYTES);
    dim3 grid((N_DIM + BN - 1) / BN, M_DIM / BM);   // (51, 16)
    gemm_relu_kernel<<<grid, 256, SMEM_BYTES>>>(fa, wh, bl, fb);
    gemm_relu_kernel<<<grid, 256, SMEM_BYTES>>>(fb, wh, bl, fa);
    gemm_relu_kernel<<<grid, 256, SMEM_BYTES>>>(fa, wh, bl, fb);
    gemm_relu_kernel<<<grid, 256, SMEM_BYTES>>>(fb, wh, bl, fa);

    head_kernel<<<2048, 160>>>(fa, wo, bo, out);
}

// round 4
// speedup vs baseline: 1.1104x; 1.1104x over previous
#include <cuda_runtime.h>
#include <cuda_fp16.h>
#include <cuda_bf16.h>
#include <cstdint>

// ---------------------------------------------------------------------------
// InversionModel R4: fp16 mma.sync GEMM, ldmatrix fragment loads (LDSM x4),
// cp.async 4-stage pipeline. tcgen05 unavailable (compute_103 virtual arch).
// ---------------------------------------------------------------------------

#define BM 128
#define BN 128
#define BK 32
#define STAGES 4
#define LDSK (BK + 8)          // 40 halves per row (pad kills LDS bank conflicts)
#define ALDB (LDSK * 2)        // 80 bytes per smem row
#define M_DIM 2048
#define N_DIM 6432
#define K_DIM 6432
#define SMEM_BYTES (2 * STAGES * BM * LDSK * (int)sizeof(__half))   // 81920

// Scratch (static device arrays; no allocation allowed)
__device__ __align__(16) __half g_act0[(size_t)M_DIM * N_DIM];
__device__ __align__(16) __half g_act1[(size_t)M_DIM * N_DIM];
__device__ __align__(16) __half g_wh[(size_t)N_DIM * K_DIM];

// ------------------------------ helpers ------------------------------------

__device__ __forceinline__ void cp16(void* dst, const void* src, bool pred) {
    uint32_t s = (uint32_t)__cvta_generic_to_shared(dst);
    int sz = pred ? 16 : 0;
    asm volatile("cp.async.cg.shared.global [%0], [%1], 16, %2;\n"
                 :: "r"(s), "l"(src), "r"(sz));
}

__device__ __forceinline__ void mma16816(float* c, const uint32_t* a, const uint32_t* b) {
    asm volatile(
        "mma.sync.aligned.m16n8k16.row.col.f32.f16.f16.f32 "
        "{%0,%1,%2,%3}, {%4,%5,%6,%7}, {%8,%9}, {%0,%1,%2,%3};\n"
        : "+f"(c[0]), "+f"(c[1]), "+f"(c[2]), "+f"(c[3])
        : "r"(a[0]), "r"(a[1]), "r"(a[2]), "r"(a[3]), "r"(b[0]), "r"(b[1]));
}

__device__ __forceinline__ void ldsm4(uint32_t& r0, uint32_t& r1, uint32_t& r2,
                                      uint32_t& r3, uint32_t addr) {
    asm volatile("ldmatrix.sync.aligned.m8n8.x4.shared.b16 {%0,%1,%2,%3}, [%4];\n"
                 : "=r"(r0), "=r"(r1), "=r"(r2), "=r"(r3) : "r"(addr));
}

// ------------------------- weight fp32 -> fp16 ------------------------------

__global__ void convert_w_kernel(const float* __restrict__ w, __half* __restrict__ wh,
                                 long long n) {
    long long i = ((long long)blockIdx.x * blockDim.x + threadIdx.x) * 4;
    if (i < n) {
        float4 v = *(const float4*)(w + i);
        *(__half2*)(wh + i)     = __floats2half2_rn(v.x, v.y);
        *(__half2*)(wh + i + 2) = __floats2half2_rn(v.z, v.w);
    }
}

// ------------------------------ frontend -----------------------------------
// One block = (batch, scale). coarse_grain -> conv1+relu+pool -> conv2+relu+pool

__global__ void frontend_kernel(const float* __restrict__ x,
                                const float* __restrict__ w1, const float* __restrict__ b1,
                                const float* __restrict__ w2, const float* __restrict__ b2,
                                __half* __restrict__ f) {
    int b = blockIdx.x;
    int sidx = blockIdx.y;           // 0,1,2 -> s = 1,2,4
    int s = 1 << sidx;
    int Lc = 480 >> sidx;
    int off = (sidx == 0) ? 0 : (sidx == 1 ? 117 : 174);

    __shared__ float xc[4 * 480];
    __shared__ float p1[16 * 238];
    __shared__ float w1s[320], w2s[2560];
    __shared__ float b1s[16], b2s[32];

    int tid = threadIdx.x;           // 128 threads
    for (int i = tid; i < 320; i += 128) w1s[i] = w1[i];
    for (int i = tid; i < 2560; i += 128) w2s[i] = w2[i];
    if (tid < 16) b1s[tid] = b1[tid];
    if (tid < 32) b2s[tid] = b2[tid];

    const float* xb = x + (size_t)b * 4 * 480;
    float inv_s = 1.0f / (float)s;
    for (int i = tid; i < 4 * Lc; i += 128) {
        int c = i / Lc, p = i % Lc;
        float sum = 0.f;
        for (int j = 0; j < s; ++j) sum += xb[c * 480 + p * s + j];
        xc[c * Lc + p] = sum * inv_s;
    }
    __syncthreads();

    int L1 = Lc - 4;
    int L1p = L1 >> 1;               // 238 / 118 / 58
    for (int i = tid; i < 16 * L1p; i += 128) {
        int o = i / L1p, q = i % L1p;
        float best = -1e30f;
        #pragma unroll
        for (int pp = 0; pp < 2; ++pp) {
            int p = 2 * q + pp;
            float acc = b1s[o];
            #pragma unroll
            for (int c = 0; c < 4; ++c)
                #pragma unroll
                for (int k = 0; k < 5; ++k)
                    acc += xc[c * Lc + p + k] * w1s[o * 20 + c * 5 + k];
            best = fmaxf(best, acc);
        }
        p1[o * L1p + q] = fmaxf(best, 0.f);
    }
    __syncthreads();

    int L2 = (L1p - 4) >> 1;         // 117 / 57 / 27
    __half* fb = f + (size_t)b * N_DIM;
    for (int i = tid; i < 32 * L2; i += 128) {
        int o2 = i / L2, q = i % L2;
        float best = -1e30f;
        #pragma unroll
        for (int pp = 0; pp < 2; ++pp) {
            int p = 2 * q + pp;
            float acc = b2s[o2];
            #pragma unroll
            for (int c1 = 0; c1 < 16; ++c1)
                #pragma unroll
                for (int k = 0; k < 5; ++k)
                    acc += p1[c1 * L1p + p + k] * w2s[o2 * 80 + c1 * 5 + k];
            best = fmaxf(best, acc);
        }
        fb[o2 * 201 + off + q] = __float2half_rn(fmaxf(best, 0.f));
    }
}

// ------------------------------- GEMM --------------------------------------
// Out[m,n] = relu( sum_k A[m,k]*W[n,k] + bias[n] ), fp16 in, fp32 acc, fp16 out.
// 128x128x32 tiles, 8 warps (2x4), warp tile 64x32, ldmatrix.x4 fragment loads.

extern __shared__ __half dynsmem[];

__global__ __launch_bounds__(256, 2)
void gemm_relu_kernel(const __half* __restrict__ A, const __half* __restrict__ W,
                      const float* __restrict__ bias, __half* __restrict__ Out) {
    __half* sA = dynsmem;                                  // [STAGES][BM][LDSK]
    __half* sB = dynsmem + STAGES * BM * LDSK;             // [STAGES][BN][LDSK]
#define AS(st, r, c) sA[((st) * BM + (r)) * LDSK + (c)]
#define BS(st, r, c) sB[((st) * BN + (r)) * LDSK + (c)]

    const int tid = threadIdx.x;
    const int bm = blockIdx.y * BM;
    const int bn = blockIdx.x * BN;
    const int warp = tid >> 5, lane = tid & 31;
    const int wm = (warp >> 2) * 64;
    const int wn = (warp & 3) * 32;
    const int g = lane >> 2, tg = lane & 3;

    const int lrow = tid >> 2;          // 0..63
    const int lcol = (tid & 3) * 8;     // 0,8,16,24

    const __half* Ag = A + (size_t)(bm + lrow) * K_DIM + lcol;
    const size_t A64 = (size_t)64 * K_DIM;
    int nrow0 = bn + lrow, nrow1 = bn + lrow + 64;
    bool v0 = nrow0 < N_DIM, v1 = nrow1 < N_DIM;
    const __half* Wg0 = W + (size_t)(v0 ? nrow0 : N_DIM - 1) * K_DIM + lcol;
    const __half* Wg1 = W + (size_t)(v1 ? nrow1 : N_DIM - 1) * K_DIM + lcol;

#define LOAD_STAGE(st, k0) do {                           \
        cp16(&AS(st, lrow, lcol),      Ag + (k0), true);  \
        cp16(&AS(st, lrow + 64, lcol), Ag + A64 + (k0), true); \
        cp16(&BS(st, lrow, lcol),      Wg0 + (k0), v0);   \
        cp16(&BS(st, lrow + 64, lcol), Wg1 + (k0), v1);   \
    } while (0)

    // ldmatrix per-lane base offsets (bytes, shared space)
    const uint32_t sAu = (uint32_t)__cvta_generic_to_shared(sA);
    const uint32_t sBu = (uint32_t)__cvta_generic_to_shared(sB);
    // A x4: lanes 0-7 rows m0-7 (k+0), 8-15 rows m8-15 (k+0),
    //       16-23 rows m0-7 (k+8), 24-31 rows m8-15 (k+8)
    const uint32_t a_off = (uint32_t)((wm + (lane & 15)) * ALDB + (lane >> 4) * 16);
    // B x4 (two n8 tiles): lanes 0-7 tile0 rows (k+0), 8-15 tile0 rows (k+8),
    //                      16-23 tile1 rows (k+0), 24-31 tile1 rows (k+8)
    const uint32_t b_off = (uint32_t)((wn + (lane >> 4) * 8 + (lane & 7)) * ALDB
                                      + ((lane >> 3) & 1) * 16);

    float acc[4][4][4];
    #pragma unroll
    for (int mt = 0; mt < 4; ++mt)
        #pragma unroll
        for (int nt = 0; nt < 4; ++nt)
            #pragma unroll
            for (int i = 0; i < 4; ++i) acc[mt][nt][i] = 0.f;

    #pragma unroll
    for (int st = 0; st < STAGES - 1; ++st) {
        LOAD_STAGE(st, st * BK);
        asm volatile("cp.async.commit_group;\n");
    }

    const int NK = K_DIM / BK;   // 201
    for (int kt = 0; kt < NK; ++kt) {
        asm volatile("cp.async.wait_group %0;\n" :: "n"(STAGES - 2));
        __syncthreads();
        int st = kt & (STAGES - 1);
        int knext = kt + STAGES - 1;
        if (knext < NK) LOAD_STAGE(knext & (STAGES - 1), knext * BK);
        asm volatile("cp.async.commit_group;\n");

        const uint32_t aS = sAu + (uint32_t)(st * BM * ALDB) + a_off;
        const uint32_t bS = sBu + (uint32_t)(st * BN * ALDB) + b_off;

        #pragma unroll
        for (int ks = 0; ks < 2; ++ks) {
            uint32_t afr[4][4], bfr[4][2];
            const uint32_t ak = aS + ks * 32;    // ks*16 halves
            const uint32_t bk = bS + ks * 32;
            #pragma unroll
            for (int mt = 0; mt < 4; ++mt)
                ldsm4(afr[mt][0], afr[mt][1], afr[mt][2], afr[mt][3],
                      ak + mt * 16 * ALDB);
            ldsm4(bfr[0][0], bfr[0][1], bfr[1][0], bfr[1][1], bk);
            ldsm4(bfr[2][0], bfr[2][1], bfr[3][0], bfr[3][1], bk + 16 * ALDB);
            #pragma unroll
            for (int mt = 0; mt < 4; ++mt)
                #pragma unroll
                for (int nt = 0; nt < 4; ++nt)
                    mma16816(acc[mt][nt], afr[mt], bfr[nt]);
        }
    }

    // Epilogue: bias + relu + fp16 store
    #pragma unroll
    for (int mt = 0; mt < 4; ++mt) {
        int row = bm + wm + mt * 16 + g;
        #pragma unroll
        for (int nt = 0; nt < 4; ++nt) {
            int col = bn + wn + nt * 8 + tg * 2;
            if (col < N_DIM) {
                float2 bb = *(const float2*)(bias + col);
                float v0a = fmaxf(acc[mt][nt][0] + bb.x, 0.f);
                float v1a = fmaxf(acc[mt][nt][1] + bb.y, 0.f);
                float v2a = fmaxf(acc[mt][nt][2] + bb.x, 0.f);
                float v3a = fmaxf(acc[mt][nt][3] + bb.y, 0.f);
                *(__half2*)(Out + (size_t)row * N_DIM + col)       = __floats2half2_rn(v0a, v1a);
                *(__half2*)(Out + (size_t)(row + 8) * N_DIM + col) = __floats2half2_rn(v2a, v3a);
            }
        }
    }
#undef AS
#undef BS
#undef LOAD_STAGE
}

// ------------------------------- head --------------------------------------

__global__ void head_kernel(const __half* __restrict__ f, const float* __restrict__ wo,
                            const float* __restrict__ bo, float* __restrict__ out) {
    int b = blockIdx.x;
    int w = threadIdx.x >> 5;        // 0..4
    int lane = threadIdx.x & 31;
    const __half* fb = f + (size_t)b * N_DIM;
    const float* wr = wo + (size_t)w * N_DIM;
    float acc = 0.f;
    for (int k = lane * 2; k < N_DIM; k += 64) {
        __half2 h = *(const __half2*)(fb + k);
        float2 wv = *(const float2*)(wr + k);
        acc += __half2float(h.x) * wv.x + __half2float(h.y) * wv.y;
    }
    #pragma unroll
    for (int o = 16; o > 0; o >>= 1) acc += __shfl_xor_sync(0xffffffffu, acc, o);
    if (lane == 0) out[b * 5 + w] = acc + bo[w];
}

// ------------------------------ launch -------------------------------------

extern "C" void kernel_launch(void* const* d_in, const int* in_sizes, int n_in,
                              void* d_out, int out_size) {
    (void)in_sizes; (void)n_in; (void)out_size;
    const float* x  = (const float*)d_in[0];
    const float* w1 = (const float*)d_in[1];
    const float* b1 = (const float*)d_in[2];
    const float* w2 = (const float*)d_in[3];
    const float* b2 = (const float*)d_in[4];
    const float* wl = (const float*)d_in[5];
    const float* bl = (const float*)d_in[6];
    const float* wo = (const float*)d_in[7];
    const float* bo = (const float*)d_in[8];
    float* out = (float*)d_out;

    __half *fa, *fb, *wh;
    cudaGetSymbolAddress((void**)&fa, g_act0);
    cudaGetSymbolAddress((void**)&fb, g_act1);
    cudaGetSymbolAddress((void**)&wh, g_wh);

    // weight conversion (fp32 -> fp16), 41,370,624 elements
    long long nW = (long long)N_DIM * K_DIM;
    convert_w_kernel<<<(unsigned)((nW / 4 + 255) / 256), 256>>>(wl, wh, nW);

    // frontend: (batch, scale) blocks
    frontend_kernel<<<dim3(2048, 3), 128>>>(x, w1, b1, w2, b2, fa);

    cudaFuncSetAttribute(gemm_relu_kernel,
                         cudaFuncAttributeMaxDynamicSharedMemorySize, SMEM_BYTES);
    dim3 grid((N_DIM + BN - 1) / BN, M_DIM / BM);   // (51, 16)
    gemm_relu_kernel<<<grid, 256, SMEM_BYTES>>>(fa, wh, bl, fb);
    gemm_relu_kernel<<<grid, 256, SMEM_BYTES>>>(fb, wh, bl, fa);
    gemm_relu_kernel<<<grid, 256, SMEM_BYTES>>>(fa, wh, bl, fb);
    gemm_relu_kernel<<<grid, 256, SMEM_BYTES>>>(fb, wh, bl, fa);

    head_kernel<<<2048, 160>>>(fa, wo, bo, out);
}